// round 2
// baseline (speedup 1.0000x reference)
#include <cuda_runtime.h>
#include <cuda_bf16.h>
#include <cstdint>

#define ULL unsigned long long

__device__ float g_routing[4096 * 8 * 6];

__device__ __forceinline__ ULL dup2(float x) {
    ULL r; asm("mov.b64 %0, {%1, %1};" : "=l"(r) : "f"(x)); return r;
}
__device__ __forceinline__ void fma2(ULL& acc, ULL a, ULL b) {
    asm("fma.rn.f32x2 %0, %1, %2, %0;" : "+l"(acc) : "l"(a), "l"(b));
}
__device__ __forceinline__ float2 unpack2(ULL v) {
    float2 f; asm("mov.b64 {%0, %1}, %2;" : "=f"(f.x), "=f"(f.y) : "l"(v)); return f;
}
__device__ __forceinline__ float fast_tanh(float x) {
    float e = __expf(2.0f * x);
    return 1.0f - __fdividef(2.0f, e + 1.0f);
}

// ---------------- routing kernel: grid (64, 8) x 256 ----------------
__global__ __launch_bounds__(256, 1) void routing_kernel(
    const float* __restrict__ x,
    const float* __restrict__ Wr1, const float* __restrict__ br1,
    const float* __restrict__ Wr2, const float* __restrict__ br2)
{
    extern __shared__ char smraw[];
    float* xs = (float*)smraw;          // 64*512
    float* w1 = xs + 64 * 512;          // 512*32
    float* r1 = w1 + 512 * 32;          // 64*32
    float* w2 = r1 + 64 * 32;           // 192
    float* b1 = w2 + 192;               // 32
    float* b2 = b1 + 32;                // 8

    const int s = blockIdx.y;
    const int b0 = blockIdx.x * 64;
    const int tid = threadIdx.x;

    for (int i = tid; i < 64 * 512 / 4; i += 256) {
        int row = i >> 7, c4 = i & 127;
        ((float4*)xs)[i] = *(const float4*)(x + (size_t)(b0 + row) * 4096 + s * 512 + c4 * 4);
    }
    const float* w1g = Wr1 + (size_t)s * 512 * 32;
    for (int i = tid; i < 512 * 32 / 4; i += 256)
        ((float4*)w1)[i] = ((const float4*)w1g)[i];
    if (tid < 32)  b1[tid] = br1[s * 32 + tid];
    if (tid < 192) w2[tid] = Wr2[s * 192 + tid];
    if (tid < 6)   b2[tid] = br2[s * 6 + tid];
    __syncthreads();

    {   // r1 = relu(x @ Wr1 + br1), thread = (h, 8 rows)
        int h = tid & 31, rg = tid >> 5;
        float acc[8];
#pragma unroll
        for (int r = 0; r < 8; ++r) acc[r] = 0.f;
        for (int k = 0; k < 512; ++k) {
            float w = w1[k * 32 + h];
#pragma unroll
            for (int r = 0; r < 8; ++r)
                acc[r] = fmaf(xs[(rg * 8 + r) * 512 + k], w, acc[r]);
        }
#pragma unroll
        for (int r = 0; r < 8; ++r)
            r1[(rg * 8 + r) * 32 + h] = fmaxf(acc[r] + b1[h], 0.f);
    }
    __syncthreads();

    if (tid < 64) {  // logits + softmax, one thread per row
        float lg[6];
#pragma unroll
        for (int e = 0; e < 6; ++e) lg[e] = b2[e];
        for (int h = 0; h < 32; ++h) {
            float rv = r1[tid * 32 + h];
#pragma unroll
            for (int e = 0; e < 6; ++e) lg[e] = fmaf(rv, w2[h * 6 + e], lg[e]);
        }
        float mx = lg[0];
#pragma unroll
        for (int e = 1; e < 6; ++e) mx = fmaxf(mx, lg[e]);
        float sum = 0.f;
#pragma unroll
        for (int e = 0; e < 6; ++e) { lg[e] = __expf(lg[e] - mx); sum += lg[e]; }
        float inv = 1.f / sum;
        int r = (b0 + tid) * 8 + s;
#pragma unroll
        for (int e = 0; e < 6; ++e) g_routing[r * 6 + e] = lg[e] * inv;
    }
}

// ------------- GEMM chunk: out[32][128] = tanh(A[32][K] @ W[K][128] + b) -------------
template <bool ABF16, bool OBF16>
__device__ __forceinline__ void gemm_chunk(
    const void* __restrict__ Asm, int lda, int K,
    const float* __restrict__ Wg, int ldw,
    float* __restrict__ wst,
    const float* __restrict__ biasg,
    void* __restrict__ Osm, int ldo, int ocol)
{
    const int tid = threadIdx.x;
    const int warp = tid >> 5, lane = tid & 31;
    const int cx = lane & 3, ry = lane >> 2;
    const int colb = warp * 16 + cx * 4;
    const int row0 = ry * 4;

    ULL acc[4][2];
#pragma unroll
    for (int r = 0; r < 4; ++r) { acc[r][0] = 0ull; acc[r][1] = 0ull; }

    const int nst = K >> 5;
    int sk[4], sc[4];
#pragma unroll
    for (int j = 0; j < 4; ++j) {
        int f = tid + 256 * j;
        sk[j] = f >> 5;
        sc[j] = (f & 31) << 2;
    }

    float4 pf[4];
#pragma unroll
    for (int j = 0; j < 4; ++j)
        pf[j] = *(const float4*)(Wg + (size_t)sk[j] * ldw + sc[j]);
    __syncthreads();
#pragma unroll
    for (int j = 0; j < 4; ++j)
        *(float4*)(wst + sk[j] * 128 + sc[j]) = pf[j];

    for (int st = 0; st < nst; ++st) {
        if (st + 1 < nst) {
#pragma unroll
            for (int j = 0; j < 4; ++j)
                pf[j] = *(const float4*)(Wg + (size_t)((st + 1) * 32 + sk[j]) * ldw + sc[j]);
        }
        __syncthreads();
        const float* wb = wst + (st & 1) * 4096 + colb;

#pragma unroll
        for (int kk = 0; kk < 32; kk += 4) {
            float xv[4][4];
            if (ABF16) {
#pragma unroll
                for (int r = 0; r < 4; ++r) {
                    const __nv_bfloat16* p =
                        (const __nv_bfloat16*)Asm + (size_t)(row0 + r) * lda + st * 32 + kk;
                    uint2 q = *(const uint2*)p;
                    float2 f0 = __bfloat1622float2(*(__nv_bfloat162*)&q.x);
                    float2 f1 = __bfloat1622float2(*(__nv_bfloat162*)&q.y);
                    xv[r][0] = f0.x; xv[r][1] = f0.y; xv[r][2] = f1.x; xv[r][3] = f1.y;
                }
            } else {
#pragma unroll
                for (int r = 0; r < 4; ++r) {
                    float4 q = *(const float4*)((const float*)Asm +
                                                (size_t)(row0 + r) * lda + st * 32 + kk);
                    xv[r][0] = q.x; xv[r][1] = q.y; xv[r][2] = q.z; xv[r][3] = q.w;
                }
            }
#pragma unroll
            for (int u = 0; u < 4; ++u) {
                ulonglong2 wq = *(const ulonglong2*)(wb + (kk + u) * 128);
#pragma unroll
                for (int r = 0; r < 4; ++r) {
                    ULL a = dup2(xv[r][u]);
                    fma2(acc[r][0], a, wq.x);
                    fma2(acc[r][1], a, wq.y);
                }
            }
        }

        if (st + 1 < nst) {
#pragma unroll
            for (int j = 0; j < 4; ++j)
                *(float4*)(wst + ((st & 1) ^ 1) * 4096 + sk[j] * 128 + sc[j]) = pf[j];
        }
    }

    float4 bv = *(const float4*)(biasg + colb);
#pragma unroll
    for (int r = 0; r < 4; ++r) {
        float2 p0 = unpack2(acc[r][0]);
        float2 p1 = unpack2(acc[r][1]);
        float o0 = fast_tanh(p0.x + bv.x);
        float o1 = fast_tanh(p0.y + bv.y);
        float o2 = fast_tanh(p1.x + bv.z);
        float o3 = fast_tanh(p1.y + bv.w);
        int row = row0 + r;
        if (OBF16) {
            __nv_bfloat162* o =
                (__nv_bfloat162*)((__nv_bfloat16*)Osm + (size_t)row * ldo + ocol + colb);
            o[0] = __floats2bfloat162_rn(o0, o1);
            o[1] = __floats2bfloat162_rn(o2, o3);
        } else {
            float* o = (float*)Osm + (size_t)row * ldo + ocol + colb;
            *(float4*)o = make_float4(o0, o1, o2, o3);
        }
    }
}

// ---------------- main fused kernel: 1024 CTAs x 256 threads ----------------
__global__ __launch_bounds__(256, 1) void moe_kernel(
    const float* __restrict__ x,
    const float* __restrict__ We1, const float* __restrict__ be1,
    const float* __restrict__ We2, const float* __restrict__ be2,
    const float* __restrict__ We3, const float* __restrict__ be3,
    const float* __restrict__ Wa1, const float* __restrict__ ba1,
    const float* __restrict__ Wa2, const float* __restrict__ ba2,
    float* __restrict__ out)
{
    extern __shared__ char smraw[];
    float*         xs   = (float*)(smraw);                 // 32*512 f32   (64K)
    __nv_bfloat16* h1s  = (__nv_bfloat16*)(smraw + 65536); // 32*1024 bf16 (64K)
    float*         h2s  = (float*)(smraw + 131072);        // 32*512 f32   (64K)
    float*         wst  = (float*)(smraw + 196608);        // 2*4096 f32   (32K)
    float*         rout = (float*)(smraw + 229376);        // 32*6
    float*         oacc = (float*)(smraw + 230144);        // 32*4

    const int tid = threadIdx.x;
    const int r0 = blockIdx.x * 32;

    for (int i = tid; i < 32 * 512 / 4; i += 256) {
        int row = i >> 7, c4 = i & 127;
        int r = r0 + row, b = r >> 3, s = r & 7;
        ((float4*)xs)[i] = *(const float4*)(x + (size_t)b * 4096 + s * 512 + c4 * 4);
    }
    if (tid < 192) rout[tid] = g_routing[r0 * 6 + tid];
    if (tid < 128) oacc[tid] = 0.f;
    __syncthreads();

    for (int e = 0; e < 6; ++e) {
        const float* W1 = We1 + (size_t)e * 512 * 1024;
        const float* b1 = be1 + e * 1024;
        for (int nc = 0; nc < 1024; nc += 128)
            gemm_chunk<false, true>(xs, 512, 512, W1 + nc, 1024, wst, b1 + nc,
                                    h1s, 1024, nc);

        const float* W2 = We2 + (size_t)e * 1024 * 512;
        const float* b2 = be2 + e * 512;
        for (int nc = 0; nc < 512; nc += 128)
            gemm_chunk<true, false>(h1s, 1024, 1024, W2 + nc, 512, wst, b2 + nc,
                                    h2s, 512, nc);
        __syncthreads();

        const float* W3 = We3 + e * 512 * 3;
        for (int i = tid; i < 1536; i += 256) {
            int k = i / 3, o = i - k * 3;
            wst[k * 4 + o] = W3[i];
        }
        __syncthreads();
        {
            int row = tid >> 3, sl = tid & 7;
            const float* h = h2s + row * 512 + sl * 64;
            const float* w = wst + sl * 64 * 4;
            float s0 = 0.f, s1 = 0.f, s2 = 0.f;
#pragma unroll 8
            for (int k = 0; k < 64; ++k) {
                float hv = h[k];
                s0 = fmaf(hv, w[k * 4 + 0], s0);
                s1 = fmaf(hv, w[k * 4 + 1], s1);
                s2 = fmaf(hv, w[k * 4 + 2], s2);
            }
#pragma unroll
            for (int d = 4; d > 0; d >>= 1) {
                s0 += __shfl_down_sync(0xffffffffu, s0, d, 8);
                s1 += __shfl_down_sync(0xffffffffu, s1, d, 8);
                s2 += __shfl_down_sync(0xffffffffu, s2, d, 8);
            }
            if (sl == 0) {
                float rw = rout[row * 6 + e];
                oacc[row * 4 + 0] += rw * (s0 + be3[e * 3 + 0]);
                oacc[row * 4 + 1] += rw * (s1 + be3[e * 3 + 1]);
                oacc[row * 4 + 2] += rw * (s2 + be3[e * 3 + 2]);
            }
        }
        __syncthreads();
    }

    if (tid < 4) {
        float f0 = 0.f, f1 = 0.f, f2 = 0.f;
#pragma unroll
        for (int i = 0; i < 8; ++i) {
            f0 += oacc[(tid * 8 + i) * 4 + 0];
            f1 += oacc[(tid * 8 + i) * 4 + 1];
            f2 += oacc[(tid * 8 + i) * 4 + 2];
        }
        f0 *= 0.125f; f1 *= 0.125f; f2 *= 0.125f;
        float a1[16];
#pragma unroll
        for (int j = 0; j < 16; ++j) {
            float v = ba1[j] + f0 * Wa1[0 * 16 + j] + f1 * Wa1[1 * 16 + j] + f2 * Wa1[2 * 16 + j];
            a1[j] = fmaxf(v, 0.f);
        }
        int b = blockIdx.x * 4 + tid;
#pragma unroll
        for (int o = 0; o < 3; ++o) {
            float v = ba2[o];
#pragma unroll
            for (int j = 0; j < 16; ++j) v = fmaf(a1[j], Wa2[j * 3 + o], v);
            out[b * 3 + o] = v;
        }
    }
}

// ---------------- launch ----------------
extern "C" void kernel_launch(void* const* d_in, const int* in_sizes, int n_in,
                              void* d_out, int out_size) {
    const float* x   = (const float*)d_in[0];
    const float* Wr1 = (const float*)d_in[1];
    const float* br1 = (const float*)d_in[2];
    const float* Wr2 = (const float*)d_in[3];
    const float* br2 = (const float*)d_in[4];
    const float* We1 = (const float*)d_in[5];
    const float* be1 = (const float*)d_in[6];
    const float* We2 = (const float*)d_in[7];
    const float* be2 = (const float*)d_in[8];
    const float* We3 = (const float*)d_in[9];
    const float* be3 = (const float*)d_in[10];
    const float* Wa1 = (const float*)d_in[11];
    const float* ba1 = (const float*)d_in[12];
    const float* Wa2 = (const float*)d_in[13];
    const float* ba2 = (const float*)d_in[14];
    float* out = (float*)d_out;

    const int SMEM_R = (64 * 512 + 512 * 32 + 64 * 32 + 192 + 32 + 8) * 4;
    const int SMEM_M = 230144 + 512;

    cudaFuncSetAttribute(routing_kernel, cudaFuncAttributeMaxDynamicSharedMemorySize, SMEM_R);
    cudaFuncSetAttribute(moe_kernel, cudaFuncAttributeMaxDynamicSharedMemorySize, SMEM_M);

    routing_kernel<<<dim3(64, 8), 256, SMEM_R>>>(x, Wr1, br1, Wr2, br2);
    moe_kernel<<<1024, 256, SMEM_M>>>(x, We1, be1, We2, be2, We3, be3,
                                      Wa1, ba1, Wa2, ba2, out);
}

// round 3
// speedup vs baseline: 1.4808x; 1.4808x over previous
#include <cuda_runtime.h>
#include <cuda_bf16.h>
#include <cstdint>

#define ULL unsigned long long

// padded leading dims (bank-conflict-free: +4 f32 / +8 bf16 => 4-bank shift/row)
#define LDA_X  516
#define LDA_H1 1032
#define LDA_H2 516

__device__ float g_routing[4096 * 8 * 6];

__device__ __forceinline__ ULL dup2(float x) {
    ULL r; asm("mov.b64 %0, {%1, %1};" : "=l"(r) : "f"(x)); return r;
}
__device__ __forceinline__ void fma2(ULL& acc, ULL a, ULL b) {
    asm("fma.rn.f32x2 %0, %1, %2, %0;" : "+l"(acc) : "l"(a), "l"(b));
}
__device__ __forceinline__ float2 unpack2(ULL v) {
    float2 f; asm("mov.b64 {%0, %1}, %2;" : "=f"(f.x), "=f"(f.y) : "l"(v)); return f;
}
__device__ __forceinline__ float fast_tanh(float x) {
    float e = __expf(2.0f * x);
    return 1.0f - __fdividef(2.0f, e + 1.0f);
}

// ---------------- routing kernel: grid (64, 8) x 256 ----------------
__global__ __launch_bounds__(256, 1) void routing_kernel(
    const float* __restrict__ x,
    const float* __restrict__ Wr1, const float* __restrict__ br1,
    const float* __restrict__ Wr2, const float* __restrict__ br2)
{
    extern __shared__ char smraw[];
    float* xs = (float*)smraw;          // 64*512
    float* w1 = xs + 64 * 512;          // 512*32
    float* r1 = w1 + 512 * 32;          // 64*32
    float* w2 = r1 + 64 * 32;           // 192
    float* b1 = w2 + 192;               // 32
    float* b2 = b1 + 32;                // 8

    const int s = blockIdx.y;
    const int b0 = blockIdx.x * 64;
    const int tid = threadIdx.x;

    for (int i = tid; i < 64 * 512 / 4; i += 256) {
        int row = i >> 7, c4 = i & 127;
        ((float4*)xs)[i] = *(const float4*)(x + (size_t)(b0 + row) * 4096 + s * 512 + c4 * 4);
    }
    const float* w1g = Wr1 + (size_t)s * 512 * 32;
    for (int i = tid; i < 512 * 32 / 4; i += 256)
        ((float4*)w1)[i] = ((const float4*)w1g)[i];
    if (tid < 32)  b1[tid] = br1[s * 32 + tid];
    if (tid < 192) w2[tid] = Wr2[s * 192 + tid];
    if (tid < 6)   b2[tid] = br2[s * 6 + tid];
    __syncthreads();

    {   // r1 = relu(x @ Wr1 + br1), thread = (h, 8 rows)
        int h = tid & 31, rg = tid >> 5;
        float acc[8];
#pragma unroll
        for (int r = 0; r < 8; ++r) acc[r] = 0.f;
        for (int k = 0; k < 512; ++k) {
            float w = w1[k * 32 + h];
#pragma unroll
            for (int r = 0; r < 8; ++r)
                acc[r] = fmaf(xs[(rg * 8 + r) * 512 + k], w, acc[r]);
        }
#pragma unroll
        for (int r = 0; r < 8; ++r)
            r1[(rg * 8 + r) * 32 + h] = fmaxf(acc[r] + b1[h], 0.f);
    }
    __syncthreads();

    if (tid < 64) {  // logits + softmax, one thread per row
        float lg[6];
#pragma unroll
        for (int e = 0; e < 6; ++e) lg[e] = b2[e];
        for (int h = 0; h < 32; ++h) {
            float rv = r1[tid * 32 + h];
#pragma unroll
            for (int e = 0; e < 6; ++e) lg[e] = fmaf(rv, w2[h * 6 + e], lg[e]);
        }
        float mx = lg[0];
#pragma unroll
        for (int e = 1; e < 6; ++e) mx = fmaxf(mx, lg[e]);
        float sum = 0.f;
#pragma unroll
        for (int e = 0; e < 6; ++e) { lg[e] = __expf(lg[e] - mx); sum += lg[e]; }
        float inv = 1.f / sum;
        int r = (b0 + tid) * 8 + s;
#pragma unroll
        for (int e = 0; e < 6; ++e) g_routing[r * 6 + e] = lg[e] * inv;
    }
}

// ------------- GEMM chunk: out[32][128] = tanh(A[32][K] @ W[K][128] + b) -------------
// Thread rows: {ry, ry+8, ry+16, ry+24} (consecutive ry lanes hit consecutive rows
// => with padded lda, A-loads are bank-conflict-free).
template <bool ABF16, bool OBF16>
__device__ __forceinline__ void gemm_chunk(
    const void* __restrict__ Asm, int lda, int K,
    const float* __restrict__ Wg, int ldw,
    float* __restrict__ wst,
    const float* __restrict__ biasg,
    void* __restrict__ Osm, int ldo, int ocol)
{
    const int tid = threadIdx.x;
    const int warp = tid >> 5, lane = tid & 31;
    const int cx = lane & 3, ry = lane >> 2;
    const int colb = warp * 16 + cx * 4;

    ULL acc[4][2];
#pragma unroll
    for (int r = 0; r < 4; ++r) { acc[r][0] = 0ull; acc[r][1] = 0ull; }

    const int nst = K >> 5;
    int sk[4], sc[4];
#pragma unroll
    for (int j = 0; j < 4; ++j) {
        int f = tid + 256 * j;
        sk[j] = f >> 5;
        sc[j] = (f & 31) << 2;
    }

    float4 pf[4];
#pragma unroll
    for (int j = 0; j < 4; ++j)
        pf[j] = *(const float4*)(Wg + (size_t)sk[j] * ldw + sc[j]);
    __syncthreads();
#pragma unroll
    for (int j = 0; j < 4; ++j)
        *(float4*)(wst + sk[j] * 128 + sc[j]) = pf[j];

    for (int st = 0; st < nst; ++st) {
        if (st + 1 < nst) {
#pragma unroll
            for (int j = 0; j < 4; ++j)
                pf[j] = *(const float4*)(Wg + (size_t)((st + 1) * 32 + sk[j]) * ldw + sc[j]);
        }
        __syncthreads();
        const float* wb = wst + (st & 1) * 4096 + colb;

#pragma unroll
        for (int kk = 0; kk < 32; kk += 4) {
            float xv[4][4];
            if (ABF16) {
#pragma unroll
                for (int r = 0; r < 4; ++r) {
                    const __nv_bfloat16* p =
                        (const __nv_bfloat16*)Asm + (size_t)(ry + 8 * r) * lda + st * 32 + kk;
                    uint2 q = *(const uint2*)p;
                    float2 f0 = __bfloat1622float2(*(__nv_bfloat162*)&q.x);
                    float2 f1 = __bfloat1622float2(*(__nv_bfloat162*)&q.y);
                    xv[r][0] = f0.x; xv[r][1] = f0.y; xv[r][2] = f1.x; xv[r][3] = f1.y;
                }
            } else {
#pragma unroll
                for (int r = 0; r < 4; ++r) {
                    float4 q = *(const float4*)((const float*)Asm +
                                                (size_t)(ry + 8 * r) * lda + st * 32 + kk);
                    xv[r][0] = q.x; xv[r][1] = q.y; xv[r][2] = q.z; xv[r][3] = q.w;
                }
            }
#pragma unroll
            for (int u = 0; u < 4; ++u) {
                ulonglong2 wq = *(const ulonglong2*)(wb + (kk + u) * 128);
#pragma unroll
                for (int r = 0; r < 4; ++r) {
                    ULL a = dup2(xv[r][u]);
                    fma2(acc[r][0], a, wq.x);
                    fma2(acc[r][1], a, wq.y);
                }
            }
        }

        if (st + 1 < nst) {
#pragma unroll
            for (int j = 0; j < 4; ++j)
                *(float4*)(wst + ((st & 1) ^ 1) * 4096 + sk[j] * 128 + sc[j]) = pf[j];
        }
    }

    float4 bv = *(const float4*)(biasg + colb);
#pragma unroll
    for (int r = 0; r < 4; ++r) {
        float2 p0 = unpack2(acc[r][0]);
        float2 p1 = unpack2(acc[r][1]);
        float o0 = fast_tanh(p0.x + bv.x);
        float o1 = fast_tanh(p0.y + bv.y);
        float o2 = fast_tanh(p1.x + bv.z);
        float o3 = fast_tanh(p1.y + bv.w);
        int row = ry + 8 * r;
        if (OBF16) {
            __nv_bfloat162* o =
                (__nv_bfloat162*)((__nv_bfloat16*)Osm + (size_t)row * ldo + ocol + colb);
            o[0] = __floats2bfloat162_rn(o0, o1);
            o[1] = __floats2bfloat162_rn(o2, o3);
        } else {
            float* o = (float*)Osm + (size_t)row * ldo + ocol + colb;
            *(float4*)o = make_float4(o0, o1, o2, o3);
        }
    }
}

// ---------------- main fused kernel: 1024 CTAs x 256 threads ----------------
__global__ __launch_bounds__(256, 1) void moe_kernel(
    const float* __restrict__ x,
    const float* __restrict__ We1, const float* __restrict__ be1,
    const float* __restrict__ We2, const float* __restrict__ be2,
    const float* __restrict__ We3, const float* __restrict__ be3,
    const float* __restrict__ Wa1, const float* __restrict__ ba1,
    const float* __restrict__ Wa2, const float* __restrict__ ba2,
    float* __restrict__ out)
{
    extern __shared__ char smraw[];
    // sizes (bytes): xs 32*516*4=66048 | h1 32*1032*2=66048 | h2 32*516*4=66048
    //                wst 32768 | rout 768 | oacc 512  => total 232192 (<232448)
    float*         xs   = (float*)(smraw);
    __nv_bfloat16* h1s  = (__nv_bfloat16*)(smraw + 66048);
    float*         h2s  = (float*)(smraw + 132096);
    float*         wst  = (float*)(smraw + 198144);
    float*         rout = (float*)(smraw + 230912);
    float*         oacc = (float*)(smraw + 231680);

    const int tid = threadIdx.x;
    const int r0 = blockIdx.x * 32;

    for (int i = tid; i < 32 * 512 / 4; i += 256) {
        int row = i >> 7, c4 = i & 127;
        int r = r0 + row, b = r >> 3, s = r & 7;
        *(float4*)(xs + (size_t)row * LDA_X + c4 * 4) =
            *(const float4*)(x + (size_t)b * 4096 + s * 512 + c4 * 4);
    }
    if (tid < 192) rout[tid] = g_routing[r0 * 6 + tid];
    if (tid < 128) oacc[tid] = 0.f;
    __syncthreads();

    for (int e = 0; e < 6; ++e) {
        const float* W1 = We1 + (size_t)e * 512 * 1024;
        const float* b1 = be1 + e * 1024;
        for (int nc = 0; nc < 1024; nc += 128)
            gemm_chunk<false, true>(xs, LDA_X, 512, W1 + nc, 1024, wst, b1 + nc,
                                    h1s, LDA_H1, nc);

        const float* W2 = We2 + (size_t)e * 1024 * 512;
        const float* b2 = be2 + e * 512;
        for (int nc = 0; nc < 512; nc += 128)
            gemm_chunk<true, false>(h1s, LDA_H1, 1024, W2 + nc, 512, wst, b2 + nc,
                                    h2s, LDA_H2, nc);
        __syncthreads();

        const float* W3 = We3 + e * 512 * 3;
        for (int i = tid; i < 1536; i += 256) {
            int k = i / 3, o = i - k * 3;
            wst[k * 4 + o] = W3[i];
        }
        __syncthreads();
        {
            int row = tid >> 3, sl = tid & 7;
            const float* h = h2s + (size_t)row * LDA_H2 + sl * 64;
            const float* w = wst + sl * 64 * 4;
            float s0 = 0.f, s1 = 0.f, s2 = 0.f;
#pragma unroll 8
            for (int k = 0; k < 64; ++k) {
                float hv = h[k];
                s0 = fmaf(hv, w[k * 4 + 0], s0);
                s1 = fmaf(hv, w[k * 4 + 1], s1);
                s2 = fmaf(hv, w[k * 4 + 2], s2);
            }
#pragma unroll
            for (int d = 4; d > 0; d >>= 1) {
                s0 += __shfl_down_sync(0xffffffffu, s0, d, 8);
                s1 += __shfl_down_sync(0xffffffffu, s1, d, 8);
                s2 += __shfl_down_sync(0xffffffffu, s2, d, 8);
            }
            if (sl == 0) {
                float rw = rout[row * 6 + e];
                oacc[row * 4 + 0] += rw * (s0 + be3[e * 3 + 0]);
                oacc[row * 4 + 1] += rw * (s1 + be3[e * 3 + 1]);
                oacc[row * 4 + 2] += rw * (s2 + be3[e * 3 + 2]);
            }
        }
        __syncthreads();
    }

    if (tid < 4) {
        float f0 = 0.f, f1 = 0.f, f2 = 0.f;
#pragma unroll
        for (int i = 0; i < 8; ++i) {
            f0 += oacc[(tid * 8 + i) * 4 + 0];
            f1 += oacc[(tid * 8 + i) * 4 + 1];
            f2 += oacc[(tid * 8 + i) * 4 + 2];
        }
        f0 *= 0.125f; f1 *= 0.125f; f2 *= 0.125f;
        float a1[16];
#pragma unroll
        for (int j = 0; j < 16; ++j) {
            float v = ba1[j] + f0 * Wa1[0 * 16 + j] + f1 * Wa1[1 * 16 + j] + f2 * Wa1[2 * 16 + j];
            a1[j] = fmaxf(v, 0.f);
        }
        int b = blockIdx.x * 4 + tid;
#pragma unroll
        for (int o = 0; o < 3; ++o) {
            float v = ba2[o];
#pragma unroll
            for (int j = 0; j < 16; ++j) v = fmaf(a1[j], Wa2[j * 3 + o], v);
            out[b * 3 + o] = v;
        }
    }
}

// ---------------- launch ----------------
extern "C" void kernel_launch(void* const* d_in, const int* in_sizes, int n_in,
                              void* d_out, int out_size) {
    const float* x   = (const float*)d_in[0];
    const float* Wr1 = (const float*)d_in[1];
    const float* br1 = (const float*)d_in[2];
    const float* Wr2 = (const float*)d_in[3];
    const float* br2 = (const float*)d_in[4];
    const float* We1 = (const float*)d_in[5];
    const float* be1 = (const float*)d_in[6];
    const float* We2 = (const float*)d_in[7];
    const float* be2 = (const float*)d_in[8];
    const float* We3 = (const float*)d_in[9];
    const float* be3 = (const float*)d_in[10];
    const float* Wa1 = (const float*)d_in[11];
    const float* ba1 = (const float*)d_in[12];
    const float* Wa2 = (const float*)d_in[13];
    const float* ba2 = (const float*)d_in[14];
    float* out = (float*)d_out;

    const int SMEM_R = (64 * 512 + 512 * 32 + 64 * 32 + 192 + 32 + 8) * 4;
    const int SMEM_M = 232192;

    cudaFuncSetAttribute(routing_kernel, cudaFuncAttributeMaxDynamicSharedMemorySize, SMEM_R);
    cudaFuncSetAttribute(moe_kernel, cudaFuncAttributeMaxDynamicSharedMemorySize, SMEM_M);

    routing_kernel<<<dim3(64, 8), 256, SMEM_R>>>(x, Wr1, br1, Wr2, br2);
    moe_kernel<<<1024, 256, SMEM_M>>>(x, We1, be1, We2, be2, We3, be3,
                                      Wa1, ba1, Wa2, ba2, out);
}

// round 4
// speedup vs baseline: 7.0732x; 4.7767x over previous
#include <cuda_runtime.h>
#include <cuda_bf16.h>
#include <cstdint>

// =======================================================================
// bf16 tensor-core (mma.sync m16n8k16) fused MoE-PINN
// CTA = 64 rows (8 batch items). 8 warps, warp tile 32x32, N-chunk 128.
// Weights pre-converted to bf16 in __device__ scratch (stream from L2).
// L3 fused into L2 epilogue (h2 never materialized).
// =======================================================================

__device__ __nv_bfloat16 g_We1b[6 * 512 * 1024];
__device__ __nv_bfloat16 g_We2b[6 * 1024 * 512];
__device__ float g_routing[32768 * 6];

__device__ __forceinline__ float fast_tanh(float x) {
    float e = __expf(2.0f * x);
    return 1.0f - __fdividef(2.0f, e + 1.0f);
}
__device__ __forceinline__ uint32_t smem_u32(const void* p) {
    return (uint32_t)__cvta_generic_to_shared(p);
}
__device__ __forceinline__ void ldsm_x4(uint32_t (&r)[4], uint32_t a) {
    asm volatile("ldmatrix.sync.aligned.m8n8.x4.shared.b16 {%0,%1,%2,%3}, [%4];"
        : "=r"(r[0]), "=r"(r[1]), "=r"(r[2]), "=r"(r[3]) : "r"(a));
}
__device__ __forceinline__ void ldsm_x4_t(uint32_t (&r)[4], uint32_t a) {
    asm volatile("ldmatrix.sync.aligned.m8n8.x4.trans.shared.b16 {%0,%1,%2,%3}, [%4];"
        : "=r"(r[0]), "=r"(r[1]), "=r"(r[2]), "=r"(r[3]) : "r"(a));
}
__device__ __forceinline__ void mma_bf16(float (&d)[4], const uint32_t (&a)[4],
                                         uint32_t b0, uint32_t b1) {
    asm volatile(
        "mma.sync.aligned.m16n8k16.row.col.f32.bf16.bf16.f32 "
        "{%0,%1,%2,%3}, {%4,%5,%6,%7}, {%8,%9}, {%0,%1,%2,%3};"
        : "+f"(d[0]), "+f"(d[1]), "+f"(d[2]), "+f"(d[3])
        : "r"(a[0]), "r"(a[1]), "r"(a[2]), "r"(a[3]), "r"(b0), "r"(b1));
}

// ---------------- prep: convert We1/We2 to bf16 ----------------
__global__ __launch_bounds__(256) void prep_kernel(
    const float* __restrict__ We1, const float* __restrict__ We2)
{
    const size_t N4 = (size_t)6 * 512 * 1024 / 4;  // 786432 float4 per array
    size_t i = (size_t)blockIdx.x * 256 + threadIdx.x;
    if (i < N4) {
        float4 v = ((const float4*)We1)[i];
        ((__nv_bfloat162*)g_We1b)[i * 2]     = __floats2bfloat162_rn(v.x, v.y);
        ((__nv_bfloat162*)g_We1b)[i * 2 + 1] = __floats2bfloat162_rn(v.z, v.w);
        float4 w = ((const float4*)We2)[i];
        ((__nv_bfloat162*)g_We2b)[i * 2]     = __floats2bfloat162_rn(w.x, w.y);
        ((__nv_bfloat162*)g_We2b)[i * 2 + 1] = __floats2bfloat162_rn(w.z, w.w);
    }
}

// ---------------- routing kernel: grid (64, 8) x 256 (fp32, unchanged) -------
__global__ __launch_bounds__(256, 1) void routing_kernel(
    const float* __restrict__ x,
    const float* __restrict__ Wr1, const float* __restrict__ br1,
    const float* __restrict__ Wr2, const float* __restrict__ br2)
{
    extern __shared__ char smraw[];
    float* xs = (float*)smraw;
    float* w1 = xs + 64 * 512;
    float* r1 = w1 + 512 * 32;
    float* w2 = r1 + 64 * 32;
    float* b1 = w2 + 192;
    float* b2 = b1 + 32;

    const int s = blockIdx.y;
    const int b0 = blockIdx.x * 64;
    const int tid = threadIdx.x;

    for (int i = tid; i < 64 * 512 / 4; i += 256) {
        int row = i >> 7, c4 = i & 127;
        ((float4*)xs)[i] = *(const float4*)(x + (size_t)(b0 + row) * 4096 + s * 512 + c4 * 4);
    }
    const float* w1g = Wr1 + (size_t)s * 512 * 32;
    for (int i = tid; i < 512 * 32 / 4; i += 256)
        ((float4*)w1)[i] = ((const float4*)w1g)[i];
    if (tid < 32)  b1[tid] = br1[s * 32 + tid];
    if (tid < 192) w2[tid] = Wr2[s * 192 + tid];
    if (tid < 6)   b2[tid] = br2[s * 6 + tid];
    __syncthreads();

    {
        int h = tid & 31, rg = tid >> 5;
        float acc[8];
#pragma unroll
        for (int r = 0; r < 8; ++r) acc[r] = 0.f;
        for (int k = 0; k < 512; ++k) {
            float w = w1[k * 32 + h];
#pragma unroll
            for (int r = 0; r < 8; ++r)
                acc[r] = fmaf(xs[(rg * 8 + r) * 512 + k], w, acc[r]);
        }
#pragma unroll
        for (int r = 0; r < 8; ++r)
            r1[(rg * 8 + r) * 32 + h] = fmaxf(acc[r] + b1[h], 0.f);
    }
    __syncthreads();

    if (tid < 64) {
        float lg[6];
#pragma unroll
        for (int e = 0; e < 6; ++e) lg[e] = b2[e];
        for (int h = 0; h < 32; ++h) {
            float rv = r1[tid * 32 + h];
#pragma unroll
            for (int e = 0; e < 6; ++e) lg[e] = fmaf(rv, w2[h * 6 + e], lg[e]);
        }
        float mx = lg[0];
#pragma unroll
        for (int e = 1; e < 6; ++e) mx = fmaxf(mx, lg[e]);
        float sum = 0.f;
#pragma unroll
        for (int e = 0; e < 6; ++e) { lg[e] = __expf(lg[e] - mx); sum += lg[e]; }
        float inv = 1.f / sum;
        int r = (b0 + tid) * 8 + s;
#pragma unroll
        for (int e = 0; e < 6; ++e) g_routing[r * 6 + e] = lg[e] * inv;
    }
}

// ---------------- tensor-core GEMM chunk ----------------
// D[64,128] = A[64,K] @ W[K,128] (+bias, tanh). MODE 0: store bf16 to h1.
// MODE 1: fuse L3 (accumulate s[4][3] += tanh(d)*We3[col][:]).
#define LDA_X 520
#define LDA_H1 1032
#define WS_STRIDE 136
#define WS_BUF (32 * WS_STRIDE)

template <int MODE>
__device__ __forceinline__ void mma_chunk(
    const __nv_bfloat16* __restrict__ Asm, int lda, int K,
    const __nv_bfloat16* __restrict__ Wg, int ldw,
    __nv_bfloat16* __restrict__ ws,
    const float* __restrict__ biasg,
    __nv_bfloat16* __restrict__ h1out, int nc,
    const float* __restrict__ we3s, float (*s)[3])
{
    const int tid = threadIdx.x;
    const int lane = tid & 31, warp = tid >> 5;
    const int wr = warp >> 2, wc = warp & 3;
    const int rowbase = wr * 32;
    const int colbase = wc * 32;
    const int li = lane & 15;   // row within 16
    const int lj = lane >> 4;   // 0/1 -> +8 in k (or n)

    float c[2][4][4];
#pragma unroll
    for (int mt = 0; mt < 2; ++mt)
#pragma unroll
        for (int nt = 0; nt < 4; ++nt)
#pragma unroll
            for (int v = 0; v < 4; ++v) c[mt][nt][v] = 0.f;

    // weight staging indices: thread fills row r0s, 16 bf16 at c0s
    const int e0 = tid * 2;
    const int r0s = e0 >> 4;
    const int c0s = (e0 & 15) * 8;
    const int nst = K >> 5;

    uint4 pf0, pf1;
    {
        const __nv_bfloat16* g = Wg + (size_t)r0s * ldw + c0s;
        pf0 = *(const uint4*)g;
        pf1 = *(const uint4*)(g + 8);
    }
    __syncthreads();
    {
        __nv_bfloat16* d = ws + r0s * WS_STRIDE + c0s;
        *(uint4*)d = pf0;
        *(uint4*)(d + 8) = pf1;
    }

    for (int st = 0; st < nst; ++st) {
        if (st + 1 < nst) {
            const __nv_bfloat16* g = Wg + (size_t)((st + 1) * 32 + r0s) * ldw + c0s;
            pf0 = *(const uint4*)g;
            pf1 = *(const uint4*)(g + 8);
        }
        __syncthreads();
        const __nv_bfloat16* wb = ws + (st & 1) * WS_BUF;

#pragma unroll
        for (int kk = 0; kk < 2; ++kk) {
            const int k0 = st * 32 + kk * 16;
            uint32_t a[2][4];
#pragma unroll
            for (int mt = 0; mt < 2; ++mt) {
                const __nv_bfloat16* ap =
                    Asm + (size_t)(rowbase + mt * 16 + li) * lda + k0 + lj * 8;
                ldsm_x4(a[mt], smem_u32(ap));
            }
            uint32_t b[2][4];
#pragma unroll
            for (int g2 = 0; g2 < 2; ++g2) {
                const __nv_bfloat16* bp =
                    wb + (kk * 16 + li) * WS_STRIDE + colbase + g2 * 16 + lj * 8;
                ldsm_x4_t(b[g2], smem_u32(bp));
            }
#pragma unroll
            for (int mt = 0; mt < 2; ++mt)
#pragma unroll
                for (int nt = 0; nt < 4; ++nt)
                    mma_bf16(c[mt][nt], a[mt], b[nt >> 1][(nt & 1) * 2],
                             b[nt >> 1][(nt & 1) * 2 + 1]);
        }

        if (st + 1 < nst) {
            __nv_bfloat16* d = ws + ((st & 1) ^ 1) * WS_BUF + r0s * WS_STRIDE + c0s;
            *(uint4*)d = pf0;
            *(uint4*)(d + 8) = pf1;
        }
    }

    // epilogue
#pragma unroll
    for (int mt = 0; mt < 2; ++mt) {
#pragma unroll
        for (int nt = 0; nt < 4; ++nt) {
            const int colc = colbase + nt * 8 + 2 * (lane & 3);  // within chunk
            float2 bb = *(const float2*)(biasg + colc);
            float t0 = fast_tanh(c[mt][nt][0] + bb.x);
            float t1 = fast_tanh(c[mt][nt][1] + bb.y);
            float t2 = fast_tanh(c[mt][nt][2] + bb.x);
            float t3 = fast_tanh(c[mt][nt][3] + bb.y);
            const int ra = rowbase + mt * 16 + (lane >> 2);
            if (MODE == 0) {
                __nv_bfloat162 p0 = __floats2bfloat162_rn(t0, t1);
                __nv_bfloat162 p1 = __floats2bfloat162_rn(t2, t3);
                *(__nv_bfloat162*)&h1out[(size_t)ra * LDA_H1 + nc + colc] = p0;
                *(__nv_bfloat162*)&h1out[(size_t)(ra + 8) * LDA_H1 + nc + colc] = p1;
            } else {
                const int cg = nc + colc;
                float4 w3a = *(const float4*)(we3s + (size_t)cg * 4);
                float4 w3b = *(const float4*)(we3s + (size_t)(cg + 1) * 4);
                s[mt * 2 + 0][0] += t0 * w3a.x + t1 * w3b.x;
                s[mt * 2 + 0][1] += t0 * w3a.y + t1 * w3b.y;
                s[mt * 2 + 0][2] += t0 * w3a.z + t1 * w3b.z;
                s[mt * 2 + 1][0] += t2 * w3a.x + t3 * w3b.x;
                s[mt * 2 + 1][1] += t2 * w3a.y + t3 * w3b.y;
                s[mt * 2 + 1][2] += t2 * w3a.z + t3 * w3b.z;
            }
        }
    }
}

// ---------------- main fused kernel: 512 CTAs x 256 threads ----------------
// smem (bytes): xs 66560 | h1 132096 | ws 17408 | we3s 8192 | rout 1536
//               eacc 1024 | oacc 1024   => 227840
__global__ __launch_bounds__(256, 1) void moe_kernel(
    const float* __restrict__ x,
    const float* __restrict__ be1, const float* __restrict__ be2,
    const float* __restrict__ We3, const float* __restrict__ be3,
    const float* __restrict__ Wa1, const float* __restrict__ ba1,
    const float* __restrict__ Wa2, const float* __restrict__ ba2,
    float* __restrict__ out)
{
    extern __shared__ char smraw[];
    __nv_bfloat16* xs   = (__nv_bfloat16*)(smraw);
    __nv_bfloat16* h1s  = (__nv_bfloat16*)(smraw + 66560);
    __nv_bfloat16* ws   = (__nv_bfloat16*)(smraw + 198656);
    float*         we3s = (float*)(smraw + 216064);
    float*         rout = (float*)(smraw + 224256);
    float*         eacc = (float*)(smraw + 225792);
    float*         oacc = (float*)(smraw + 226816);

    const int tid = threadIdx.x;
    const int lane = tid & 31, warp = tid >> 5;
    const int wr = warp >> 2;
    const int r0 = blockIdx.x * 64;

    // load x (flat [32768][512]) -> bf16 smem
    for (int i = tid; i < 64 * 512 / 4; i += 256) {
        int row = i >> 7, c4 = i & 127;
        float4 v = *(const float4*)(x + (size_t)(r0 + row) * 512 + c4 * 4);
        __nv_bfloat162* d = (__nv_bfloat162*)&xs[(size_t)row * LDA_X + c4 * 4];
        d[0] = __floats2bfloat162_rn(v.x, v.y);
        d[1] = __floats2bfloat162_rn(v.z, v.w);
    }
    if (tid < 384) rout[tid] = g_routing[(size_t)r0 * 6 + tid];
    eacc[tid] = 0.f;
    oacc[tid] = 0.f;
    __syncthreads();

    for (int e = 0; e < 6; ++e) {
        // load We3[e] into smem (pad to 4)
        for (int i = tid; i < 1536; i += 256) {
            int k = i / 3, o = i - k * 3;
            we3s[k * 4 + o] = We3[(size_t)e * 1536 + i];
        }
        // (mma_chunk prologue __syncthreads orders this write before use)

        // L1: h1 = tanh(x @ We1 + be1), 8 chunks of N=128
        const __nv_bfloat16* W1 = g_We1b + (size_t)e * 512 * 1024;
        const float* b1 = be1 + e * 1024;
        for (int nc = 0; nc < 1024; nc += 128)
            mma_chunk<0>(xs, LDA_X, 512, W1 + nc, 1024, ws, b1 + nc,
                         h1s, nc, nullptr, nullptr);

        // L2+L3 fused: 4 chunks of N=128
        float s[4][3];
#pragma unroll
        for (int rt = 0; rt < 4; ++rt)
#pragma unroll
            for (int o = 0; o < 3; ++o) s[rt][o] = 0.f;

        const __nv_bfloat16* W2 = g_We2b + (size_t)e * 1024 * 512;
        const float* b2 = be2 + e * 512;
        for (int nc = 0; nc < 512; nc += 128)
            mma_chunk<1>(h1s, LDA_H1, 1024, W2 + nc, 512, ws, b2 + nc,
                         nullptr, nc, we3s, s);

        // reduce over the 4 lanes sharing each row (lane&3)
#pragma unroll
        for (int rt = 0; rt < 4; ++rt)
#pragma unroll
            for (int o = 0; o < 3; ++o) {
                s[rt][o] += __shfl_xor_sync(0xffffffffu, s[rt][o], 1);
                s[rt][o] += __shfl_xor_sync(0xffffffffu, s[rt][o], 2);
            }
        if ((lane & 3) == 0) {
#pragma unroll
            for (int rt = 0; rt < 4; ++rt) {
                int row = wr * 32 + (rt >> 1) * 16 + (lane >> 2) + 8 * (rt & 1);
#pragma unroll
                for (int o = 0; o < 3; ++o)
                    atomicAdd(&eacc[row * 4 + o], s[rt][o]);
            }
        }
        __syncthreads();
        if (tid < 192) {
            int row = tid / 3, o = tid - row * 3;
            oacc[row * 4 + o] += rout[row * 6 + e] * (eacc[row * 4 + o] + be3[e * 3 + o]);
        }
        __syncthreads();
        eacc[tid] = 0.f;
        __syncthreads();
    }

    // block mean + aggregator (8 batch items per CTA)
    if (tid < 8) {
        float f0 = 0.f, f1 = 0.f, f2 = 0.f;
#pragma unroll
        for (int i = 0; i < 8; ++i) {
            f0 += oacc[(tid * 8 + i) * 4 + 0];
            f1 += oacc[(tid * 8 + i) * 4 + 1];
            f2 += oacc[(tid * 8 + i) * 4 + 2];
        }
        f0 *= 0.125f; f1 *= 0.125f; f2 *= 0.125f;
        float a1[16];
#pragma unroll
        for (int j = 0; j < 16; ++j) {
            float v = ba1[j] + f0 * Wa1[j] + f1 * Wa1[16 + j] + f2 * Wa1[32 + j];
            a1[j] = fmaxf(v, 0.f);
        }
        int b = blockIdx.x * 8 + tid;
#pragma unroll
        for (int o = 0; o < 3; ++o) {
            float v = ba2[o];
#pragma unroll
            for (int j = 0; j < 16; ++j) v = fmaf(a1[j], Wa2[j * 3 + o], v);
            out[b * 3 + o] = v;
        }
    }
}

// ---------------- launch ----------------
extern "C" void kernel_launch(void* const* d_in, const int* in_sizes, int n_in,
                              void* d_out, int out_size) {
    const float* x   = (const float*)d_in[0];
    const float* Wr1 = (const float*)d_in[1];
    const float* br1 = (const float*)d_in[2];
    const float* Wr2 = (const float*)d_in[3];
    const float* br2 = (const float*)d_in[4];
    const float* We1 = (const float*)d_in[5];
    const float* be1 = (const float*)d_in[6];
    const float* We2 = (const float*)d_in[7];
    const float* be2 = (const float*)d_in[8];
    const float* We3 = (const float*)d_in[9];
    const float* be3 = (const float*)d_in[10];
    const float* Wa1 = (const float*)d_in[11];
    const float* ba1 = (const float*)d_in[12];
    const float* Wa2 = (const float*)d_in[13];
    const float* ba2 = (const float*)d_in[14];
    float* out = (float*)d_out;

    const int SMEM_R = (64 * 512 + 512 * 32 + 64 * 32 + 192 + 32 + 8) * 4;
    const int SMEM_M = 227840;

    cudaFuncSetAttribute(routing_kernel, cudaFuncAttributeMaxDynamicSharedMemorySize, SMEM_R);
    cudaFuncSetAttribute(moe_kernel, cudaFuncAttributeMaxDynamicSharedMemorySize, SMEM_M);

    prep_kernel<<<3072, 256>>>(We1, We2);
    routing_kernel<<<dim3(64, 8), 256, SMEM_R>>>(x, Wr1, br1, Wr2, br2);
    moe_kernel<<<512, 256, SMEM_M>>>(x, be1, be2, We3, be3,
                                     Wa1, ba1, Wa2, ba2, out);
}

// round 5
// speedup vs baseline: 8.4315x; 1.1920x over previous
#include <cuda_runtime.h>
#include <cuda_bf16.h>
#include <cstdint>

// =======================================================================
// bf16 mma.sync fused MoE-PINN, cp.async 4-deep weight pipeline (16-k stages)
// =======================================================================

__device__ __nv_bfloat16 g_We1b[6 * 512 * 1024];
__device__ __nv_bfloat16 g_We2b[6 * 1024 * 512];
__device__ float g_routing[32768 * 6];

__device__ __forceinline__ float fast_tanh(float x) {
    float e = __expf(2.0f * x);
    return 1.0f - __fdividef(2.0f, e + 1.0f);
}
__device__ __forceinline__ uint32_t smem_u32(const void* p) {
    return (uint32_t)__cvta_generic_to_shared(p);
}
__device__ __forceinline__ void ldsm_x4(uint32_t (&r)[4], uint32_t a) {
    asm volatile("ldmatrix.sync.aligned.m8n8.x4.shared.b16 {%0,%1,%2,%3}, [%4];"
        : "=r"(r[0]), "=r"(r[1]), "=r"(r[2]), "=r"(r[3]) : "r"(a));
}
__device__ __forceinline__ void ldsm_x4_t(uint32_t (&r)[4], uint32_t a) {
    asm volatile("ldmatrix.sync.aligned.m8n8.x4.trans.shared.b16 {%0,%1,%2,%3}, [%4];"
        : "=r"(r[0]), "=r"(r[1]), "=r"(r[2]), "=r"(r[3]) : "r"(a));
}
__device__ __forceinline__ void mma_bf16(float (&d)[4], const uint32_t (&a)[4],
                                         uint32_t b0, uint32_t b1) {
    asm volatile(
        "mma.sync.aligned.m16n8k16.row.col.f32.bf16.bf16.f32 "
        "{%0,%1,%2,%3}, {%4,%5,%6,%7}, {%8,%9}, {%0,%1,%2,%3};"
        : "+f"(d[0]), "+f"(d[1]), "+f"(d[2]), "+f"(d[3])
        : "r"(a[0]), "r"(a[1]), "r"(a[2]), "r"(a[3]), "r"(b0), "r"(b1));
}
__device__ __forceinline__ void cp16(uint32_t dst, const void* src) {
    asm volatile("cp.async.cg.shared.global [%0], [%1], 16;" :: "r"(dst), "l"(src));
}
__device__ __forceinline__ void cp_commit() {
    asm volatile("cp.async.commit_group;");
}
__device__ __forceinline__ void cp_wait2() {
    asm volatile("cp.async.wait_group 2;");
}

// ---------------- prep: convert We1/We2 to bf16 ----------------
__global__ __launch_bounds__(256) void prep_kernel(
    const float* __restrict__ We1, const float* __restrict__ We2)
{
    const size_t N4 = (size_t)6 * 512 * 1024 / 4;
    size_t i = (size_t)blockIdx.x * 256 + threadIdx.x;
    if (i < N4) {
        float4 v = ((const float4*)We1)[i];
        ((__nv_bfloat162*)g_We1b)[i * 2]     = __floats2bfloat162_rn(v.x, v.y);
        ((__nv_bfloat162*)g_We1b)[i * 2 + 1] = __floats2bfloat162_rn(v.z, v.w);
        float4 w = ((const float4*)We2)[i];
        ((__nv_bfloat162*)g_We2b)[i * 2]     = __floats2bfloat162_rn(w.x, w.y);
        ((__nv_bfloat162*)g_We2b)[i * 2 + 1] = __floats2bfloat162_rn(w.z, w.w);
    }
}

// ---------------- routing kernel (fp32, unchanged) ----------------
__global__ __launch_bounds__(256, 1) void routing_kernel(
    const float* __restrict__ x,
    const float* __restrict__ Wr1, const float* __restrict__ br1,
    const float* __restrict__ Wr2, const float* __restrict__ br2)
{
    extern __shared__ char smraw[];
    float* xs = (float*)smraw;
    float* w1 = xs + 64 * 512;
    float* r1 = w1 + 512 * 32;
    float* w2 = r1 + 64 * 32;
    float* b1 = w2 + 192;
    float* b2 = b1 + 32;

    const int s = blockIdx.y;
    const int b0 = blockIdx.x * 64;
    const int tid = threadIdx.x;

    for (int i = tid; i < 64 * 512 / 4; i += 256) {
        int row = i >> 7, c4 = i & 127;
        ((float4*)xs)[i] = *(const float4*)(x + (size_t)(b0 + row) * 4096 + s * 512 + c4 * 4);
    }
    const float* w1g = Wr1 + (size_t)s * 512 * 32;
    for (int i = tid; i < 512 * 32 / 4; i += 256)
        ((float4*)w1)[i] = ((const float4*)w1g)[i];
    if (tid < 32)  b1[tid] = br1[s * 32 + tid];
    if (tid < 192) w2[tid] = Wr2[s * 192 + tid];
    if (tid < 6)   b2[tid] = br2[s * 6 + tid];
    __syncthreads();

    {
        int h = tid & 31, rg = tid >> 5;
        float acc[8];
#pragma unroll
        for (int r = 0; r < 8; ++r) acc[r] = 0.f;
        for (int k = 0; k < 512; ++k) {
            float w = w1[k * 32 + h];
#pragma unroll
            for (int r = 0; r < 8; ++r)
                acc[r] = fmaf(xs[(rg * 8 + r) * 512 + k], w, acc[r]);
        }
#pragma unroll
        for (int r = 0; r < 8; ++r)
            r1[(rg * 8 + r) * 32 + h] = fmaxf(acc[r] + b1[h], 0.f);
    }
    __syncthreads();

    if (tid < 64) {
        float lg[6];
#pragma unroll
        for (int e = 0; e < 6; ++e) lg[e] = b2[e];
        for (int h = 0; h < 32; ++h) {
            float rv = r1[tid * 32 + h];
#pragma unroll
            for (int e = 0; e < 6; ++e) lg[e] = fmaf(rv, w2[h * 6 + e], lg[e]);
        }
        float mx = lg[0];
#pragma unroll
        for (int e = 1; e < 6; ++e) mx = fmaxf(mx, lg[e]);
        float sum = 0.f;
#pragma unroll
        for (int e = 0; e < 6; ++e) { lg[e] = __expf(lg[e] - mx); sum += lg[e]; }
        float inv = 1.f / sum;
        int r = (b0 + tid) * 8 + s;
#pragma unroll
        for (int e = 0; e < 6; ++e) g_routing[r * 6 + e] = lg[e] * inv;
    }
}

// ---------------- tensor-core GEMM chunk, cp.async pipeline ----------------
#define LDA_X 520
#define LDA_H1 1032
#define WS_STRIDE 136
#define WS_BUF_E (16 * WS_STRIDE)      // elems per buffer
#define WS_BUF_B (WS_BUF_E * 2)        // bytes per buffer

template <int MODE>
__device__ __forceinline__ void mma_chunk(
    const __nv_bfloat16* __restrict__ Asm, int lda, int K,
    const __nv_bfloat16* __restrict__ Wg, int ldw,
    const __nv_bfloat16* __restrict__ ws, uint32_t ws_u32,
    const float* __restrict__ biasg,
    __nv_bfloat16* __restrict__ h1out, int nc,
    const float* __restrict__ we3s, float (*s)[3])
{
    const int tid = threadIdx.x;
    const int lane = tid & 31, warp = tid >> 5;
    const int wr = warp >> 2, wc = warp & 3;
    const int rowbase = wr * 32, colbase = wc * 32;
    const int li = lane & 15, lj = lane >> 4;

    float c[2][4][4];
#pragma unroll
    for (int mt = 0; mt < 2; ++mt)
#pragma unroll
        for (int nt = 0; nt < 4; ++nt)
#pragma unroll
            for (int v = 0; v < 4; ++v) c[mt][nt][v] = 0.f;

    // cp.async assignment: 16 rows x 128 cols per stage, 16B per thread
    const int crow = tid >> 4;            // 0..15
    const int ccol = (tid & 15) * 8;      // 0..120
    const uint32_t dst0 = ws_u32 + (uint32_t)(crow * WS_STRIDE + ccol) * 2;
    const __nv_bfloat16* src0 = Wg + (size_t)crow * ldw + ccol;
    const int nst = K >> 4;               // 32 or 64

#pragma unroll
    for (int q = 0; q < 3; ++q) {
        cp16(dst0 + (uint32_t)q * WS_BUF_B, src0 + (size_t)q * 16 * ldw);
        cp_commit();
    }

    const __nv_bfloat16* a0 = Asm + (size_t)(rowbase + li) * lda + lj * 8;
    const __nv_bfloat16* a1 = a0 + (size_t)16 * lda;
    const __nv_bfloat16* bp = ws + li * WS_STRIDE + colbase + lj * 8;

    for (int st = 0; st < nst; ++st) {
        cp_wait2();
        __syncthreads();
        if (st + 3 < nst)
            cp16(dst0 + (uint32_t)((st + 3) & 3) * WS_BUF_B,
                 src0 + (size_t)(st + 3) * 16 * ldw);
        cp_commit();

        uint32_t a[2][4], b[2][4];
        ldsm_x4(a[0], smem_u32(a0 + st * 16));
        ldsm_x4(a[1], smem_u32(a1 + st * 16));
        const __nv_bfloat16* wb = bp + (st & 3) * WS_BUF_E;
        ldsm_x4_t(b[0], smem_u32(wb));
        ldsm_x4_t(b[1], smem_u32(wb + 16));

#pragma unroll
        for (int mt = 0; mt < 2; ++mt)
#pragma unroll
            for (int nt = 0; nt < 4; ++nt)
                mma_bf16(c[mt][nt], a[mt], b[nt >> 1][(nt & 1) * 2],
                         b[nt >> 1][(nt & 1) * 2 + 1]);
    }

    // epilogue
#pragma unroll
    for (int mt = 0; mt < 2; ++mt) {
#pragma unroll
        for (int nt = 0; nt < 4; ++nt) {
            const int colc = colbase + nt * 8 + 2 * (lane & 3);
            float2 bb = *(const float2*)(biasg + colc);
            float t0 = fast_tanh(c[mt][nt][0] + bb.x);
            float t1 = fast_tanh(c[mt][nt][1] + bb.y);
            float t2 = fast_tanh(c[mt][nt][2] + bb.x);
            float t3 = fast_tanh(c[mt][nt][3] + bb.y);
            const int ra = rowbase + mt * 16 + (lane >> 2);
            if (MODE == 0) {
                __nv_bfloat162 p0 = __floats2bfloat162_rn(t0, t1);
                __nv_bfloat162 p1 = __floats2bfloat162_rn(t2, t3);
                *(__nv_bfloat162*)&h1out[(size_t)ra * LDA_H1 + nc + colc] = p0;
                *(__nv_bfloat162*)&h1out[(size_t)(ra + 8) * LDA_H1 + nc + colc] = p1;
            } else {
                const int cg = nc + colc;
                const float* w3a = we3s + (size_t)cg * 3;
                const float* w3b = w3a + 3;
#pragma unroll
                for (int o = 0; o < 3; ++o) {
                    float wa = w3a[o], wb2 = w3b[o];
                    s[mt * 2 + 0][o] += t0 * wa + t1 * wb2;
                    s[mt * 2 + 1][o] += t2 * wa + t3 * wb2;
                }
            }
        }
    }
}

// ---------------- main fused kernel: 512 CTAs x 256 threads ----------------
// smem: xs 66560 | h1 132096 | ws 17408 | we3s 6144 | rout 1536 | oacc 1024
//       total 224768
__global__ __launch_bounds__(256, 1) void moe_kernel(
    const float* __restrict__ x,
    const float* __restrict__ be1, const float* __restrict__ be2,
    const float* __restrict__ We3, const float* __restrict__ be3,
    const float* __restrict__ Wa1, const float* __restrict__ ba1,
    const float* __restrict__ Wa2, const float* __restrict__ ba2,
    float* __restrict__ out)
{
    extern __shared__ char smraw[];
    __nv_bfloat16* xs   = (__nv_bfloat16*)(smraw);
    __nv_bfloat16* h1s  = (__nv_bfloat16*)(smraw + 66560);
    __nv_bfloat16* ws   = (__nv_bfloat16*)(smraw + 198656);
    float*         we3s = (float*)(smraw + 216064);
    float*         rout = (float*)(smraw + 222208);
    float*         oacc = (float*)(smraw + 223744);

    const int tid = threadIdx.x;
    const int lane = tid & 31, warp = tid >> 5;
    const int wr = warp >> 2, wc = warp & 3;
    const int r0 = blockIdx.x * 64;
    const uint32_t ws_u32 = smem_u32(ws);

    for (int i = tid; i < 64 * 512 / 4; i += 256) {
        int row = i >> 7, c4 = i & 127;
        float4 v = *(const float4*)(x + (size_t)(r0 + row) * 512 + c4 * 4);
        __nv_bfloat162* d = (__nv_bfloat162*)&xs[(size_t)row * LDA_X + c4 * 4];
        d[0] = __floats2bfloat162_rn(v.x, v.y);
        d[1] = __floats2bfloat162_rn(v.z, v.w);
    }
    if (tid < 384) rout[tid] = g_routing[(size_t)r0 * 6 + tid];
    oacc[tid] = 0.f;
    __syncthreads();

    for (int e = 0; e < 6; ++e) {
        // barrier: previous expert's we3s readers + oacc atomics done before rewrite
        __syncthreads();
        for (int i = tid; i < 1536; i += 256)
            we3s[i] = We3[(size_t)e * 1536 + i];
        // (ordered before first use by the first in-loop __syncthreads of chunk 0)

        // L1: h1 = tanh(x @ We1 + be1)
        const __nv_bfloat16* W1 = g_We1b + (size_t)e * 512 * 1024;
        const float* b1 = be1 + e * 1024;
        for (int nc = 0; nc < 1024; nc += 128)
            mma_chunk<0>(xs, LDA_X, 512, W1 + nc, 1024, ws, ws_u32, b1 + nc,
                         h1s, nc, nullptr, nullptr);

        // L2+L3 fused
        float s[4][3];
#pragma unroll
        for (int rt = 0; rt < 4; ++rt)
#pragma unroll
            for (int o = 0; o < 3; ++o) s[rt][o] = 0.f;

        const __nv_bfloat16* W2 = g_We2b + (size_t)e * 1024 * 512;
        const float* b2 = be2 + e * 512;
        for (int nc = 0; nc < 512; nc += 128)
            mma_chunk<1>(h1s, LDA_H1, 1024, W2 + nc, 512, ws, ws_u32, b2 + nc,
                         nullptr, nc, we3s, s);

        // reduce the 4 lanes sharing each row, then routing-weighted accumulate
#pragma unroll
        for (int rt = 0; rt < 4; ++rt)
#pragma unroll
            for (int o = 0; o < 3; ++o) {
                s[rt][o] += __shfl_xor_sync(0xffffffffu, s[rt][o], 1);
                s[rt][o] += __shfl_xor_sync(0xffffffffu, s[rt][o], 2);
            }
        if ((lane & 3) == 0) {
            float bz[3];
#pragma unroll
            for (int o = 0; o < 3; ++o)
                bz[o] = (wc == 0) ? be3[e * 3 + o] : 0.f;
#pragma unroll
            for (int rt = 0; rt < 4; ++rt) {
                int row = wr * 32 + (rt >> 1) * 16 + (lane >> 2) + 8 * (rt & 1);
                float rw = rout[row * 6 + e];
#pragma unroll
                for (int o = 0; o < 3; ++o)
                    atomicAdd(&oacc[row * 4 + o], rw * (s[rt][o] + bz[o]));
            }
        }
    }
    __syncthreads();

    // block mean + aggregator (8 batch items per CTA)
    if (tid < 8) {
        float f0 = 0.f, f1 = 0.f, f2 = 0.f;
#pragma unroll
        for (int i = 0; i < 8; ++i) {
            f0 += oacc[(tid * 8 + i) * 4 + 0];
            f1 += oacc[(tid * 8 + i) * 4 + 1];
            f2 += oacc[(tid * 8 + i) * 4 + 2];
        }
        f0 *= 0.125f; f1 *= 0.125f; f2 *= 0.125f;
        float a1[16];
#pragma unroll
        for (int j = 0; j < 16; ++j) {
            float v = ba1[j] + f0 * Wa1[j] + f1 * Wa1[16 + j] + f2 * Wa1[32 + j];
            a1[j] = fmaxf(v, 0.f);
        }
        int b = blockIdx.x * 8 + tid;
#pragma unroll
        for (int o = 0; o < 3; ++o) {
            float v = ba2[o];
#pragma unroll
            for (int j = 0; j < 16; ++j) v = fmaf(a1[j], Wa2[j * 3 + o], v);
            out[b * 3 + o] = v;
        }
    }
}

// ---------------- launch ----------------
extern "C" void kernel_launch(void* const* d_in, const int* in_sizes, int n_in,
                              void* d_out, int out_size) {
    const float* x   = (const float*)d_in[0];
    const float* Wr1 = (const float*)d_in[1];
    const float* br1 = (const float*)d_in[2];
    const float* Wr2 = (const float*)d_in[3];
    const float* br2 = (const float*)d_in[4];
    const float* We1 = (const float*)d_in[5];
    const float* be1 = (const float*)d_in[6];
    const float* We2 = (const float*)d_in[7];
    const float* be2 = (const float*)d_in[8];
    const float* We3 = (const float*)d_in[9];
    const float* be3 = (const float*)d_in[10];
    const float* Wa1 = (const float*)d_in[11];
    const float* ba1 = (const float*)d_in[12];
    const float* Wa2 = (const float*)d_in[13];
    const float* ba2 = (const float*)d_in[14];
    float* out = (float*)d_out;

    const int SMEM_R = (64 * 512 + 512 * 32 + 64 * 32 + 192 + 32 + 8) * 4;
    const int SMEM_M = 224768;

    cudaFuncSetAttribute(routing_kernel, cudaFuncAttributeMaxDynamicSharedMemorySize, SMEM_R);
    cudaFuncSetAttribute(moe_kernel, cudaFuncAttributeMaxDynamicSharedMemorySize, SMEM_M);

    prep_kernel<<<3072, 256>>>(We1, We2);
    routing_kernel<<<dim3(64, 8), 256, SMEM_R>>>(x, Wr1, br1, Wr2, br2);
    moe_kernel<<<512, 256, SMEM_M>>>(x, be1, be2, We3, be3,
                                     Wa1, ba1, Wa2, ba2, out);
}

// round 6
// speedup vs baseline: 8.4868x; 1.0066x over previous
#include <cuda_runtime.h>
#include <cuda_bf16.h>
#include <cstdint>

// =======================================================================
// bf16 mma.sync fused MoE-PINN, cp.async 4-deep weight pipeline (16-k stages)
// =======================================================================

__device__ __nv_bfloat16 g_We1b[6 * 512 * 1024];
__device__ __nv_bfloat16 g_We2b[6 * 1024 * 512];
__device__ float g_routing[32768 * 6];

__device__ __forceinline__ float fast_tanh(float x) {
    float e = __expf(2.0f * x);
    return 1.0f - __fdividef(2.0f, e + 1.0f);
}
__device__ __forceinline__ uint32_t smem_u32(const void* p) {
    return (uint32_t)__cvta_generic_to_shared(p);
}
__device__ __forceinline__ void ldsm_x4(uint32_t (&r)[4], uint32_t a) {
    asm volatile("ldmatrix.sync.aligned.m8n8.x4.shared.b16 {%0,%1,%2,%3}, [%4];"
        : "=r"(r[0]), "=r"(r[1]), "=r"(r[2]), "=r"(r[3]) : "r"(a));
}
__device__ __forceinline__ void ldsm_x4_t(uint32_t (&r)[4], uint32_t a) {
    asm volatile("ldmatrix.sync.aligned.m8n8.x4.trans.shared.b16 {%0,%1,%2,%3}, [%4];"
        : "=r"(r[0]), "=r"(r[1]), "=r"(r[2]), "=r"(r[3]) : "r"(a));
}
__device__ __forceinline__ void mma_bf16(float (&d)[4], const uint32_t (&a)[4],
                                         uint32_t b0, uint32_t b1) {
    asm volatile(
        "mma.sync.aligned.m16n8k16.row.col.f32.bf16.bf16.f32 "
        "{%0,%1,%2,%3}, {%4,%5,%6,%7}, {%8,%9}, {%0,%1,%2,%3};"
        : "+f"(d[0]), "+f"(d[1]), "+f"(d[2]), "+f"(d[3])
        : "r"(a[0]), "r"(a[1]), "r"(a[2]), "r"(a[3]), "r"(b0), "r"(b1));
}
__device__ __forceinline__ void cp16(uint32_t dst, const void* src) {
    asm volatile("cp.async.cg.shared.global [%0], [%1], 16;" :: "r"(dst), "l"(src));
}
__device__ __forceinline__ void cp_commit() {
    asm volatile("cp.async.commit_group;");
}
__device__ __forceinline__ void cp_wait2() {
    asm volatile("cp.async.wait_group 2;");
}

// ---------------- prep: convert We1/We2 to bf16 ----------------
__global__ __launch_bounds__(256) void prep_kernel(
    const float* __restrict__ We1, const float* __restrict__ We2)
{
    const size_t N4 = (size_t)6 * 512 * 1024 / 4;
    size_t i = (size_t)blockIdx.x * 256 + threadIdx.x;
    if (i < N4) {
        float4 v = ((const float4*)We1)[i];
        ((__nv_bfloat162*)g_We1b)[i * 2]     = __floats2bfloat162_rn(v.x, v.y);
        ((__nv_bfloat162*)g_We1b)[i * 2 + 1] = __floats2bfloat162_rn(v.z, v.w);
        float4 w = ((const float4*)We2)[i];
        ((__nv_bfloat162*)g_We2b)[i * 2]     = __floats2bfloat162_rn(w.x, w.y);
        ((__nv_bfloat162*)g_We2b)[i * 2 + 1] = __floats2bfloat162_rn(w.z, w.w);
    }
}

// ---------------- routing kernel (fp32, unchanged) ----------------
__global__ __launch_bounds__(256, 1) void routing_kernel(
    const float* __restrict__ x,
    const float* __restrict__ Wr1, const float* __restrict__ br1,
    const float* __restrict__ Wr2, const float* __restrict__ br2)
{
    extern __shared__ char smraw[];
    float* xs = (float*)smraw;
    float* w1 = xs + 64 * 512;
    float* r1 = w1 + 512 * 32;
    float* w2 = r1 + 64 * 32;
    float* b1 = w2 + 192;
    float* b2 = b1 + 32;

    const int s = blockIdx.y;
    const int b0 = blockIdx.x * 64;
    const int tid = threadIdx.x;

    for (int i = tid; i < 64 * 512 / 4; i += 256) {
        int row = i >> 7, c4 = i & 127;
        ((float4*)xs)[i] = *(const float4*)(x + (size_t)(b0 + row) * 4096 + s * 512 + c4 * 4);
    }
    const float* w1g = Wr1 + (size_t)s * 512 * 32;
    for (int i = tid; i < 512 * 32 / 4; i += 256)
        ((float4*)w1)[i] = ((const float4*)w1g)[i];
    if (tid < 32)  b1[tid] = br1[s * 32 + tid];
    if (tid < 192) w2[tid] = Wr2[s * 192 + tid];
    if (tid < 6)   b2[tid] = br2[s * 6 + tid];
    __syncthreads();

    {
        int h = tid & 31, rg = tid >> 5;
        float acc[8];
#pragma unroll
        for (int r = 0; r < 8; ++r) acc[r] = 0.f;
        for (int k = 0; k < 512; ++k) {
            float w = w1[k * 32 + h];
#pragma unroll
            for (int r = 0; r < 8; ++r)
                acc[r] = fmaf(xs[(rg * 8 + r) * 512 + k], w, acc[r]);
        }
#pragma unroll
        for (int r = 0; r < 8; ++r)
            r1[(rg * 8 + r) * 32 + h] = fmaxf(acc[r] + b1[h], 0.f);
    }
    __syncthreads();

    if (tid < 64) {
        float lg[6];
#pragma unroll
        for (int e = 0; e < 6; ++e) lg[e] = b2[e];
        for (int h = 0; h < 32; ++h) {
            float rv = r1[tid * 32 + h];
#pragma unroll
            for (int e = 0; e < 6; ++e) lg[e] = fmaf(rv, w2[h * 6 + e], lg[e]);
        }
        float mx = lg[0];
#pragma unroll
        for (int e = 1; e < 6; ++e) mx = fmaxf(mx, lg[e]);
        float sum = 0.f;
#pragma unroll
        for (int e = 0; e < 6; ++e) { lg[e] = __expf(lg[e] - mx); sum += lg[e]; }
        float inv = 1.f / sum;
        int r = (b0 + tid) * 8 + s;
#pragma unroll
        for (int e = 0; e < 6; ++e) g_routing[r * 6 + e] = lg[e] * inv;
    }
}

// ---------------- tensor-core GEMM chunk, cp.async pipeline ----------------
#define LDA_X 520
#define LDA_H1 1032
#define WS_STRIDE 136
#define WS_BUF_E (16 * WS_STRIDE)      // elems per buffer
#define WS_BUF_B (WS_BUF_E * 2)        // bytes per buffer

template <int MODE>
__device__ __forceinline__ void mma_chunk(
    const __nv_bfloat16* __restrict__ Asm, int lda, int K,
    const __nv_bfloat16* __restrict__ Wg, int ldw,
    const __nv_bfloat16* __restrict__ ws, uint32_t ws_u32,
    const float* __restrict__ biasg,
    __nv_bfloat16* __restrict__ h1out, int nc,
    const float* __restrict__ we3s, float (*s)[3])
{
    const int tid = threadIdx.x;
    const int lane = tid & 31, warp = tid >> 5;
    const int wr = warp >> 2, wc = warp & 3;
    const int rowbase = wr * 32, colbase = wc * 32;
    const int li = lane & 15, lj = lane >> 4;

    float c[2][4][4];
#pragma unroll
    for (int mt = 0; mt < 2; ++mt)
#pragma unroll
        for (int nt = 0; nt < 4; ++nt)
#pragma unroll
            for (int v = 0; v < 4; ++v) c[mt][nt][v] = 0.f;

    // cp.async assignment: 16 rows x 128 cols per stage, 16B per thread
    const int crow = tid >> 4;            // 0..15
    const int ccol = (tid & 15) * 8;      // 0..120
    const uint32_t dst0 = ws_u32 + (uint32_t)(crow * WS_STRIDE + ccol) * 2;
    const __nv_bfloat16* src0 = Wg + (size_t)crow * ldw + ccol;
    const int nst = K >> 4;               // 32 or 64

#pragma unroll
    for (int q = 0; q < 3; ++q) {
        cp16(dst0 + (uint32_t)q * WS_BUF_B, src0 + (size_t)q * 16 * ldw);
        cp_commit();
    }

    const __nv_bfloat16* a0 = Asm + (size_t)(rowbase + li) * lda + lj * 8;
    const __nv_bfloat16* a1 = a0 + (size_t)16 * lda;
    const __nv_bfloat16* bp = ws + li * WS_STRIDE + colbase + lj * 8;

    for (int st = 0; st < nst; ++st) {
        cp_wait2();
        __syncthreads();
        if (st + 3 < nst)
            cp16(dst0 + (uint32_t)((st + 3) & 3) * WS_BUF_B,
                 src0 + (size_t)(st + 3) * 16 * ldw);
        cp_commit();

        uint32_t a[2][4], b[2][4];
        ldsm_x4(a[0], smem_u32(a0 + st * 16));
        ldsm_x4(a[1], smem_u32(a1 + st * 16));
        const __nv_bfloat16* wb = bp + (st & 3) * WS_BUF_E;
        ldsm_x4_t(b[0], smem_u32(wb));
        ldsm_x4_t(b[1], smem_u32(wb + 16));

#pragma unroll
        for (int mt = 0; mt < 2; ++mt)
#pragma unroll
            for (int nt = 0; nt < 4; ++nt)
                mma_bf16(c[mt][nt], a[mt], b[nt >> 1][(nt & 1) * 2],
                         b[nt >> 1][(nt & 1) * 2 + 1]);
    }

    // epilogue
#pragma unroll
    for (int mt = 0; mt < 2; ++mt) {
#pragma unroll
        for (int nt = 0; nt < 4; ++nt) {
            const int colc = colbase + nt * 8 + 2 * (lane & 3);
            float2 bb = *(const float2*)(biasg + colc);
            float t0 = fast_tanh(c[mt][nt][0] + bb.x);
            float t1 = fast_tanh(c[mt][nt][1] + bb.y);
            float t2 = fast_tanh(c[mt][nt][2] + bb.x);
            float t3 = fast_tanh(c[mt][nt][3] + bb.y);
            const int ra = rowbase + mt * 16 + (lane >> 2);
            if (MODE == 0) {
                __nv_bfloat162 p0 = __floats2bfloat162_rn(t0, t1);
                __nv_bfloat162 p1 = __floats2bfloat162_rn(t2, t3);
                *(__nv_bfloat162*)&h1out[(size_t)ra * LDA_H1 + nc + colc] = p0;
                *(__nv_bfloat162*)&h1out[(size_t)(ra + 8) * LDA_H1 + nc + colc] = p1;
            } else {
                const int cg = nc + colc;
                const float* w3a = we3s + (size_t)cg * 3;
                const float* w3b = w3a + 3;
#pragma unroll
                for (int o = 0; o < 3; ++o) {
                    float wa = w3a[o], wb2 = w3b[o];
                    s[mt * 2 + 0][o] += t0 * wa + t1 * wb2;
                    s[mt * 2 + 1][o] += t2 * wa + t3 * wb2;
                }
            }
        }
    }
}

// ---------------- main fused kernel: 512 CTAs x 256 threads ----------------
// smem: xs 66560 | h1 132096 | ws 17408 | we3s 6144 | rout 1536 | oacc 1024
//       total 224768
__global__ __launch_bounds__(256, 1) void moe_kernel(
    const float* __restrict__ x,
    const float* __restrict__ be1, const float* __restrict__ be2,
    const float* __restrict__ We3, const float* __restrict__ be3,
    const float* __restrict__ Wa1, const float* __restrict__ ba1,
    const float* __restrict__ Wa2, const float* __restrict__ ba2,
    float* __restrict__ out)
{
    extern __shared__ char smraw[];
    __nv_bfloat16* xs   = (__nv_bfloat16*)(smraw);
    __nv_bfloat16* h1s  = (__nv_bfloat16*)(smraw + 66560);
    __nv_bfloat16* ws   = (__nv_bfloat16*)(smraw + 198656);
    float*         we3s = (float*)(smraw + 216064);
    float*         rout = (float*)(smraw + 222208);
    float*         oacc = (float*)(smraw + 223744);

    const int tid = threadIdx.x;
    const int lane = tid & 31, warp = tid >> 5;
    const int wr = warp >> 2, wc = warp & 3;
    const int r0 = blockIdx.x * 64;
    const uint32_t ws_u32 = smem_u32(ws);

    for (int i = tid; i < 64 * 512 / 4; i += 256) {
        int row = i >> 7, c4 = i & 127;
        float4 v = *(const float4*)(x + (size_t)(r0 + row) * 512 + c4 * 4);
        __nv_bfloat162* d = (__nv_bfloat162*)&xs[(size_t)row * LDA_X + c4 * 4];
        d[0] = __floats2bfloat162_rn(v.x, v.y);
        d[1] = __floats2bfloat162_rn(v.z, v.w);
    }
    if (tid < 384) rout[tid] = g_routing[(size_t)r0 * 6 + tid];
    oacc[tid] = 0.f;
    __syncthreads();

    for (int e = 0; e < 6; ++e) {
        // barrier: previous expert's we3s readers + oacc atomics done before rewrite
        __syncthreads();
        for (int i = tid; i < 1536; i += 256)
            we3s[i] = We3[(size_t)e * 1536 + i];
        // (ordered before first use by the first in-loop __syncthreads of chunk 0)

        // L1: h1 = tanh(x @ We1 + be1)
        const __nv_bfloat16* W1 = g_We1b + (size_t)e * 512 * 1024;
        const float* b1 = be1 + e * 1024;
        for (int nc = 0; nc < 1024; nc += 128)
            mma_chunk<0>(xs, LDA_X, 512, W1 + nc, 1024, ws, ws_u32, b1 + nc,
                         h1s, nc, nullptr, nullptr);

        // L2+L3 fused
        float s[4][3];
#pragma unroll
        for (int rt = 0; rt < 4; ++rt)
#pragma unroll
            for (int o = 0; o < 3; ++o) s[rt][o] = 0.f;

        const __nv_bfloat16* W2 = g_We2b + (size_t)e * 1024 * 512;
        const float* b2 = be2 + e * 512;
        for (int nc = 0; nc < 512; nc += 128)
            mma_chunk<1>(h1s, LDA_H1, 1024, W2 + nc, 512, ws, ws_u32, b2 + nc,
                         nullptr, nc, we3s, s);

        // reduce the 4 lanes sharing each row, then routing-weighted accumulate
#pragma unroll
        for (int rt = 0; rt < 4; ++rt)
#pragma unroll
            for (int o = 0; o < 3; ++o) {
                s[rt][o] += __shfl_xor_sync(0xffffffffu, s[rt][o], 1);
                s[rt][o] += __shfl_xor_sync(0xffffffffu, s[rt][o], 2);
            }
        if ((lane & 3) == 0) {
            float bz[3];
#pragma unroll
            for (int o = 0; o < 3; ++o)
                bz[o] = (wc == 0) ? be3[e * 3 + o] : 0.f;
#pragma unroll
            for (int rt = 0; rt < 4; ++rt) {
                int row = wr * 32 + (rt >> 1) * 16 + (lane >> 2) + 8 * (rt & 1);
                float rw = rout[row * 6 + e];
#pragma unroll
                for (int o = 0; o < 3; ++o)
                    atomicAdd(&oacc[row * 4 + o], rw * (s[rt][o] + bz[o]));
            }
        }
    }
    __syncthreads();

    // block mean + aggregator (8 batch items per CTA)
    if (tid < 8) {
        float f0 = 0.f, f1 = 0.f, f2 = 0.f;
#pragma unroll
        for (int i = 0; i < 8; ++i) {
            f0 += oacc[(tid * 8 + i) * 4 + 0];
            f1 += oacc[(tid * 8 + i) * 4 + 1];
            f2 += oacc[(tid * 8 + i) * 4 + 2];
        }
        f0 *= 0.125f; f1 *= 0.125f; f2 *= 0.125f;
        float a1[16];
#pragma unroll
        for (int j = 0; j < 16; ++j) {
            float v = ba1[j] + f0 * Wa1[j] + f1 * Wa1[16 + j] + f2 * Wa1[32 + j];
            a1[j] = fmaxf(v, 0.f);
        }
        int b = blockIdx.x * 8 + tid;
#pragma unroll
        for (int o = 0; o < 3; ++o) {
            float v = ba2[o];
#pragma unroll
            for (int j = 0; j < 16; ++j) v = fmaf(a1[j], Wa2[j * 3 + o], v);
            out[b * 3 + o] = v;
        }
    }
}

// ---------------- launch ----------------
extern "C" void kernel_launch(void* const* d_in, const int* in_sizes, int n_in,
                              void* d_out, int out_size) {
    const float* x   = (const float*)d_in[0];
    const float* Wr1 = (const float*)d_in[1];
    const float* br1 = (const float*)d_in[2];
    const float* Wr2 = (const float*)d_in[3];
    const float* br2 = (const float*)d_in[4];
    const float* We1 = (const float*)d_in[5];
    const float* be1 = (const float*)d_in[6];
    const float* We2 = (const float*)d_in[7];
    const float* be2 = (const float*)d_in[8];
    const float* We3 = (const float*)d_in[9];
    const float* be3 = (const float*)d_in[10];
    const float* Wa1 = (const float*)d_in[11];
    const float* ba1 = (const float*)d_in[12];
    const float* Wa2 = (const float*)d_in[13];
    const float* ba2 = (const float*)d_in[14];
    float* out = (float*)d_out;

    const int SMEM_R = (64 * 512 + 512 * 32 + 64 * 32 + 192 + 32 + 8) * 4;
    const int SMEM_M = 224768;

    cudaFuncSetAttribute(routing_kernel, cudaFuncAttributeMaxDynamicSharedMemorySize, SMEM_R);
    cudaFuncSetAttribute(moe_kernel, cudaFuncAttributeMaxDynamicSharedMemorySize, SMEM_M);

    prep_kernel<<<3072, 256>>>(We1, We2);
    routing_kernel<<<dim3(64, 8), 256, SMEM_R>>>(x, Wr1, br1, Wr2, br2);
    moe_kernel<<<512, 256, SMEM_M>>>(x, be1, be2, We3, be3,
                                     Wa1, ba1, Wa2, ba2, out);
}